// round 4
// baseline (speedup 1.0000x reference)
#include <cuda_runtime.h>
#include <stdint.h>

// Problem constants (fixed by the reference setup)
#define Bn 16
#define Pn 784
#define Dn 10000
#define Ln 1000
#define Cn 10

#define WSTRIDE 320   // padded words per row (320*32 = 10240 >= 10000)
#define NSLAB   10    // 10 slabs of 32 words each

// Scratch (allocation-free: device globals)
__device__ uint32_t g_vbits[Ln * WSTRIDE];   // sign bits of value_weight
__device__ uint32_t g_pbits[Pn * WSTRIDE];   // sign bits of position_weight
__device__ int      g_idx[Bn * Pn];          // level index per (b, pixel)
__device__ float    g_partial[NSLAB * Bn * Cn];

// ---------------------------------------------------------------------------
// Kernel 1: compute idx, pack sign bits of both bipolar tables.
// NATURAL bit layout: word w, bit l  <->  dim d = w*32 + l.
// Warp-task = 1024 dims of one row. Lane l packs its own word (32 consecutive
// dims) from 8 float4 loads — no ballots, no cross-lane traffic. Per-warp the
// 8 loads cover a contiguous 4KB span, fully coalesced.
// ---------------------------------------------------------------------------
__global__ void __launch_bounds__(256) pack_kernel(const float* __restrict__ x,
                                                   const float* __restrict__ posw,
                                                   const float* __restrict__ valw)
{
    const int tid     = blockIdx.x * blockDim.x + threadIdx.x;
    const int nthread = gridDim.x * blockDim.x;

    // level index: idx = clamp(rint(x*999), 0, 999)  (rintf = half-to-even)
    for (int i = tid; i < Bn * Pn; i += nthread) {
        int q = (int)rintf(x[i] * 999.0f);
        g_idx[i] = min(max(q, 0), Ln - 1);
    }

    const int lane   = threadIdx.x & 31;
    const int warpId = tid >> 5;
    const int nWarps = nthread >> 5;
    const int totalTasks = (Ln + Pn) * 10;   // 10 x 1024-dim tasks per row

    for (int task = warpId; task < totalTasks; task += nWarps) {
        int row = task / 10;
        int s   = task - row * 10;
        const float* src;
        uint32_t* dst;
        if (row < Ln) {
            src = valw + (size_t)row * Dn;
            dst = g_vbits + row * WSTRIDE;
        } else {
            src = posw + (size_t)(row - Ln) * Dn;
            dst = g_pbits + (row - Ln) * WSTRIDE;
        }

        const int dbase = s * 1024 + lane * 32;
        uint32_t word = 0;
#pragma unroll
        for (int i = 0; i < 8; i++) {
            int d0 = dbase + i * 4;              // multiple of 4; Dn % 4 == 0
            if (d0 < Dn) {
                float4 v = *reinterpret_cast<const float4*>(src + d0);
                uint32_t n =  (__float_as_uint(v.x) >> 31)
                           | ((__float_as_uint(v.y) >> 31) << 1)
                           | ((__float_as_uint(v.z) >> 31) << 2)
                           | ((__float_as_uint(v.w) >> 31) << 3);
                word |= n << (i * 4);
            }
        }
        dst[s * 32 + lane] = word;               // coalesced 128B per warp
    }
}

// ---------------------------------------------------------------------------
__device__ __forceinline__ void fadd(uint32_t a, uint32_t b, uint32_t cin,
                                     uint32_t& s, uint32_t& cout)
{
    uint32_t t = a ^ b;
    s    = t ^ cin;
    cout = (a & b) | (cin & t);
}

// ---------------------------------------------------------------------------
// Kernel 2: CTA = (batch, 32-word slab), 512 threads = 16 warps x 49 pixels.
// Warp lane = word within slab so all bit-table loads are 128B coalesced.
// Each warp accumulates 7 groups of 7 pixels via a 7:3 CSA compressor into
// 7 bit-planes; 16 warps reduce through smem; threshold gives enc bits;
// classify partials per slab. Fixed-order reductions, no atomics.
// ---------------------------------------------------------------------------
__global__ void __launch_bounds__(512) hdc_main_kernel(const float* __restrict__ cw)
{
    const int b    = blockIdx.x / NSLAB;
    const int slab = blockIdx.x - b * NSLAB;
    const int tid  = threadIdx.x;
    const int lane = tid & 31;
    const int warp = tid >> 5;                   // 0..15

    __shared__ int      sIdx[Pn];
    __shared__ uint32_t sRed[16][7][33];         // padded vs bank conflicts
    __shared__ uint32_t encW[32];
    __shared__ float    redS[512];

    for (int i = tid; i < Pn; i += 512) sIdx[i] = g_idx[b * Pn + i];
    __syncthreads();

    const int w = slab * 32 + lane;

    uint32_t c[7];
#pragma unroll
    for (int j = 0; j < 7; j++) c[j] = 0u;

    const int p0 = warp * 49;
    const uint32_t* __restrict__ vb = g_vbits + w;
    const uint32_t* __restrict__ pb = g_pbits + w;

    for (int g = 0; g < 7; g++) {                // 7 groups of 7 pixels
        const int pbase = p0 + g * 7;
        uint32_t t[7];
#pragma unroll
        for (int k = 0; k < 7; k++) {
            int lvl = sIdx[pbase + k];
            t[k] = __ldg(vb + lvl * WSTRIDE) ^ __ldg(pb + (pbase + k) * WSTRIDE);
        }
        // 7:3 compressor -> (s3, s4, c4) with weights 1,2,4
        uint32_t s1, c1, s2, c2, s3, c3, s4, c4;
        fadd(t[0], t[1], t[2], s1, c1);
        fadd(t[3], t[4], t[5], s2, c2);
        fadd(s1,  s2,  t[6],  s3, c3);
        fadd(c1,  c2,  c3,    s4, c4);
        // merge 3-bit value into the 7-plane counter
        uint32_t carry = c[0] & s3; c[0] ^= s3;
        uint32_t s, co;
        fadd(c[1], s4, carry, s, co); c[1] = s; carry = co;
        fadd(c[2], c4, carry, s, co); c[2] = s; carry = co;
#pragma unroll
        for (int j = 3; j < 7; j++) { uint32_t nc = c[j] ^ carry; carry &= c[j]; c[j] = nc; }
    }

#pragma unroll
    for (int j = 0; j < 7; j++) sRed[warp][j][lane] = c[j];
    __syncthreads();

    if (warp == 0) {
        uint32_t a[10];
#pragma unroll
        for (int j = 0; j < 7; j++) a[j] = sRed[0][j][lane];
        a[7] = a[8] = a[9] = 0u;
#pragma unroll
        for (int wu = 1; wu < 16; wu++) {
            uint32_t carry = 0u;
#pragma unroll
            for (int j = 0; j < 7; j++) {
                uint32_t s, co;
                fadd(a[j], sRed[wu][j][lane], carry, s, co);
                a[j] = s; carry = co;
            }
#pragma unroll
            for (int j = 7; j < 10; j++) { uint32_t nc = a[j] ^ carry; carry &= a[j]; a[j] = nc; }
        }
        // enc = +1 iff count < 392 (392 = 0b0110001000)
        uint32_t eq = ~0u, lt = 0u;
        eq &= ~a[9];
        lt |= eq & ~a[8]; eq &= a[8];
        lt |= eq & ~a[7]; eq &= a[7];
        eq &= ~a[6]; eq &= ~a[5]; eq &= ~a[4];
        lt |= eq & ~a[3];
        encW[lane] = lt;                         // bit set -> enc = +1
    }
    __syncthreads();

    // classify partials for this 1024-dim slab (natural layout: d = slab*1024+j)
    float acc = 0.0f;
    if (tid < 500) {
        const int cc   = tid % 10;
        const int slot = tid / 10;               // 0..49
        const float* __restrict__ wrow = cw + cc * Dn + slab * 1024;
        for (int j = slot; j < 1024; j += 50) {
            int d = slab * 1024 + j;
            if (d < Dn) {
                float wt = __ldg(wrow + j);
                acc += ((encW[j >> 5] >> (j & 31)) & 1u) ? wt : -wt;
            }
        }
    }
    redS[tid] = acc;
    __syncthreads();

    if (tid < 10) {
        float s = 0.0f;
#pragma unroll
        for (int slot = 0; slot < 50; slot++) s += redS[tid + slot * 10];
        g_partial[(slab * Bn + b) * Cn + tid] = s;
    }
}

// ---------------------------------------------------------------------------
// Kernel 3: deterministic final reduction over the 10 slabs.
// ---------------------------------------------------------------------------
__global__ void finalize_kernel(float* __restrict__ out)
{
    int i = threadIdx.x;
    if (i < Bn * Cn) {
        float s = 0.0f;
#pragma unroll
        for (int sl = 0; sl < NSLAB; sl++) s += g_partial[sl * Bn * Cn + i];
        out[i] = s;
    }
}

// ---------------------------------------------------------------------------
extern "C" void kernel_launch(void* const* d_in, const int* in_sizes, int n_in,
                              void* d_out, int out_size)
{
    const float* x    = (const float*)d_in[0];   // [16,28,28]
    const float* posw = (const float*)d_in[1];   // [784,10000]
    const float* valw = (const float*)d_in[2];   // [1000,10000]
    const float* cw   = (const float*)d_in[3];   // [10,10000]
    float* out = (float*)d_out;                  // [16,10]

    pack_kernel<<<1184, 256>>>(x, posw, valw);
    hdc_main_kernel<<<Bn * NSLAB, 512>>>(cw);
    finalize_kernel<<<1, 192>>>(out);
}

// round 5
// speedup vs baseline: 1.3681x; 1.3681x over previous
#include <cuda_runtime.h>
#include <stdint.h>

// Problem constants (fixed by the reference setup)
#define Bn 16
#define Pn 784
#define Dn 10000
#define Ln 1000
#define Cn 10

#define WSTRIDE 320   // padded words per row (320*32 = 10240 >= 10000)
#define NSLAB   10    // 10 slabs of 32 words each

// Scratch (allocation-free: device globals)
__device__ uint32_t g_vbits[Ln * WSTRIDE];   // sign bits of value_weight
__device__ uint32_t g_pbits[Pn * WSTRIDE];   // sign bits of position_weight
__device__ int      g_idx[Bn * Pn];          // level index per (b, pixel)
__device__ float    g_partial[NSLAB * Bn * Cn];
__device__ int      g_ctr;                   // last-CTA counter (reset each run)

// ---------------------------------------------------------------------------
// Kernel 1: compute idx, pack sign bits of both bipolar tables.
// Permuted bit layout: word w, bit l  <->  dim d = (w>>2)*128 + l*4 + (w&3).
// Warp-task = 512 dims: 4 lane-contiguous float4 loads (fully coalesced,
// 4 sectors per load instruction), sign extraction via FSETP feeding VOTE
// directly (no integer nibble assembly), 16 ballots -> 16 words, 64B store.
// ---------------------------------------------------------------------------
__global__ void __launch_bounds__(256) pack_kernel(const float* __restrict__ x,
                                                   const float* __restrict__ posw,
                                                   const float* __restrict__ valw)
{
    const int tid     = blockIdx.x * blockDim.x + threadIdx.x;
    const int nthread = gridDim.x * blockDim.x;

    if (tid == 0) g_ctr = 0;   // reset fused-finalize counter for this replay

    // level index: idx = clamp(rint(x*999), 0, 999)  (rintf = half-to-even)
    for (int i = tid; i < Bn * Pn; i += nthread) {
        int q = (int)rintf(x[i] * 999.0f);
        g_idx[i] = min(max(q, 0), Ln - 1);
    }

    const int lane   = threadIdx.x & 31;
    const int warpId = tid >> 5;
    const int nWarps = nthread >> 5;
    const int totalTasks = (Ln + Pn) * 20;   // 20 x 512-dim tasks per row

    for (int task = warpId; task < totalTasks; task += nWarps) {
        int row = task / 20;
        int s   = task - row * 20;
        const float* src;
        uint32_t* dst;
        if (row < Ln) {
            src = valw + (size_t)row * Dn;
            dst = g_vbits + row * WSTRIDE;
        } else {
            src = posw + (size_t)(row - Ln) * Dn;
            dst = g_pbits + (row - Ln) * WSTRIDE;
        }

        uint32_t myword = 0;
        if (s < 19) {
            // fast path: all 512 dims valid
            float4 v0 = *reinterpret_cast<const float4*>(src + s * 512 +   0 + lane * 4);
            float4 v1 = *reinterpret_cast<const float4*>(src + s * 512 + 128 + lane * 4);
            float4 v2 = *reinterpret_cast<const float4*>(src + s * 512 + 256 + lane * 4);
            float4 v3 = *reinterpret_cast<const float4*>(src + s * 512 + 384 + lane * 4);
#define PK(sub, vv)                                                          \
            {                                                                \
                uint32_t b0 = __ballot_sync(0xffffffffu, (vv).x < 0.0f);     \
                uint32_t b1 = __ballot_sync(0xffffffffu, (vv).y < 0.0f);     \
                uint32_t b2 = __ballot_sync(0xffffffffu, (vv).z < 0.0f);     \
                uint32_t b3 = __ballot_sync(0xffffffffu, (vv).w < 0.0f);     \
                if (lane == (sub)*4 + 0) myword = b0;                        \
                if (lane == (sub)*4 + 1) myword = b1;                        \
                if (lane == (sub)*4 + 2) myword = b2;                        \
                if (lane == (sub)*4 + 3) myword = b3;                        \
            }
            PK(0, v0) PK(1, v1) PK(2, v2) PK(3, v3)
#undef PK
        } else {
            // tail task (dims 9728..10239): per-lane validity
#pragma unroll
            for (int sub = 0; sub < 4; sub++) {
                int d0 = s * 512 + sub * 128 + lane * 4;
                bool valid = d0 < Dn;            // Dn % 4 == 0
                float4 v = make_float4(0.f, 0.f, 0.f, 0.f);
                if (valid) v = *reinterpret_cast<const float4*>(src + d0);
                uint32_t b0 = __ballot_sync(0xffffffffu, valid && v.x < 0.0f);
                uint32_t b1 = __ballot_sync(0xffffffffu, valid && v.y < 0.0f);
                uint32_t b2 = __ballot_sync(0xffffffffu, valid && v.z < 0.0f);
                uint32_t b3 = __ballot_sync(0xffffffffu, valid && v.w < 0.0f);
                if (lane == sub * 4 + 0) myword = b0;
                if (lane == sub * 4 + 1) myword = b1;
                if (lane == sub * 4 + 2) myword = b2;
                if (lane == sub * 4 + 3) myword = b3;
            }
        }
        if (lane < 16) dst[s * 16 + lane] = myword;      // coalesced 64B
    }
}

// ---------------------------------------------------------------------------
__device__ __forceinline__ void fadd(uint32_t a, uint32_t b, uint32_t cin,
                                     uint32_t& s, uint32_t& cout)
{
    uint32_t t = a ^ b;
    s    = t ^ cin;
    cout = (a & b) | (cin & t);
}

// ---------------------------------------------------------------------------
// Kernel 2: CTA = (batch, 32-word slab), 512 threads = 16 warps x 49 pixels.
// Warp lane = word within slab -> all bit-table loads 128B coalesced.
// 7:3 CSA compressor per 7-pixel group; 16-warp smem reduction; threshold;
// classify partials; the LAST CTA (atomic int counter) performs the final
// deterministic reduction and writes out. No float atomics.
// ---------------------------------------------------------------------------
__global__ void __launch_bounds__(512) hdc_main_kernel(const float* __restrict__ cw,
                                                       float* __restrict__ out)
{
    const int b    = blockIdx.x / NSLAB;
    const int slab = blockIdx.x - b * NSLAB;
    const int tid  = threadIdx.x;
    const int lane = tid & 31;
    const int warp = tid >> 5;                   // 0..15

    __shared__ int      sIdx[Pn];
    __shared__ uint32_t sRed[16][7][33];         // padded vs bank conflicts
    __shared__ uint32_t encW[32];
    __shared__ float    redS[512];
    __shared__ int      sLast;

    for (int i = tid; i < Pn; i += 512) sIdx[i] = g_idx[b * Pn + i];
    __syncthreads();

    const int w = slab * 32 + lane;

    uint32_t c[7];
#pragma unroll
    for (int j = 0; j < 7; j++) c[j] = 0u;

    const int p0 = warp * 49;
    const uint32_t* __restrict__ vb = g_vbits + w;
    const uint32_t* __restrict__ pb = g_pbits + w;

    for (int g = 0; g < 7; g++) {                // 7 groups of 7 pixels
        const int pbase = p0 + g * 7;
        uint32_t t[7];
#pragma unroll
        for (int k = 0; k < 7; k++) {
            int lvl = sIdx[pbase + k];
            t[k] = __ldg(vb + lvl * WSTRIDE) ^ __ldg(pb + (pbase + k) * WSTRIDE);
        }
        // 7:3 compressor -> (s3, s4, c4) with weights 1,2,4
        uint32_t s1, c1, s2, c2, s3, c3, s4, c4;
        fadd(t[0], t[1], t[2], s1, c1);
        fadd(t[3], t[4], t[5], s2, c2);
        fadd(s1,  s2,  t[6],  s3, c3);
        fadd(c1,  c2,  c3,    s4, c4);
        // merge 3-bit value into the 7-plane counter
        uint32_t carry = c[0] & s3; c[0] ^= s3;
        uint32_t s, co;
        fadd(c[1], s4, carry, s, co); c[1] = s; carry = co;
        fadd(c[2], c4, carry, s, co); c[2] = s; carry = co;
#pragma unroll
        for (int j = 3; j < 7; j++) { uint32_t nc = c[j] ^ carry; carry &= c[j]; c[j] = nc; }
    }

#pragma unroll
    for (int j = 0; j < 7; j++) sRed[warp][j][lane] = c[j];
    __syncthreads();

    if (warp == 0) {
        uint32_t a[10];
#pragma unroll
        for (int j = 0; j < 7; j++) a[j] = sRed[0][j][lane];
        a[7] = a[8] = a[9] = 0u;
#pragma unroll
        for (int wu = 1; wu < 16; wu++) {
            uint32_t carry = 0u;
#pragma unroll
            for (int j = 0; j < 7; j++) {
                uint32_t s, co;
                fadd(a[j], sRed[wu][j][lane], carry, s, co);
                a[j] = s; carry = co;
            }
#pragma unroll
            for (int j = 7; j < 10; j++) { uint32_t nc = a[j] ^ carry; carry &= a[j]; a[j] = nc; }
        }
        // enc = +1 iff count < 392 (392 = 0b0110001000)
        uint32_t eq = ~0u, lt = 0u;
        eq &= ~a[9];
        lt |= eq & ~a[8]; eq &= a[8];
        lt |= eq & ~a[7]; eq &= a[7];
        eq &= ~a[6]; eq &= ~a[5]; eq &= ~a[4];
        lt |= eq & ~a[3];
        encW[lane] = lt;                         // bit set -> enc = +1
    }
    __syncthreads();

    // classify partials for this 1024-dim slab (permuted layout)
    float acc = 0.0f;
    if (tid < 500) {
        const int cc   = tid % 10;
        const int slot = tid / 10;               // 0..49
        const float* __restrict__ wrow = cw + cc * Dn;
        for (int j = slot; j < 1024; j += 50) {
            int wl2 = j >> 5, l = j & 31;
            int wg  = slab * 32 + wl2;
            int d   = (wg >> 2) * 128 + (l << 2) + (wg & 3);
            if (d < Dn) {
                float wt = __ldg(wrow + d);
                acc += ((encW[wl2] >> l) & 1u) ? wt : -wt;
            }
        }
    }
    redS[tid] = acc;
    __syncthreads();

    if (tid < 10) {
        float s = 0.0f;
#pragma unroll
        for (int slot = 0; slot < 50; slot++) s += redS[tid + slot * 10];
        g_partial[(slab * Bn + b) * Cn + tid] = s;
    }

    // ---- fused finalize: last CTA reduces g_partial and writes out ----
    __syncthreads();
    if (tid == 0) {
        __threadfence();                         // publish g_partial writes
        int prev = atomicAdd(&g_ctr, 1);
        sLast = (prev == Bn * NSLAB - 1);
    }
    __syncthreads();
    if (sLast) {
        __threadfence();                         // acquire all g_partial
        if (tid < Bn * Cn) {
            float s = 0.0f;
#pragma unroll
            for (int sl = 0; sl < NSLAB; sl++) s += g_partial[sl * Bn * Cn + tid];
            out[tid] = s;
        }
        if (tid == 0) g_ctr = 0;                 // reset for next replay
    }
}

// ---------------------------------------------------------------------------
extern "C" void kernel_launch(void* const* d_in, const int* in_sizes, int n_in,
                              void* d_out, int out_size)
{
    const float* x    = (const float*)d_in[0];   // [16,28,28]
    const float* posw = (const float*)d_in[1];   // [784,10000]
    const float* valw = (const float*)d_in[2];   // [1000,10000]
    const float* cw   = (const float*)d_in[3];   // [10,10000]
    float* out = (float*)d_out;                  // [16,10]

    pack_kernel<<<1184, 256>>>(x, posw, valw);
    hdc_main_kernel<<<Bn * NSLAB, 512>>>(cw, out);
}

// round 6
// speedup vs baseline: 1.5273x; 1.1164x over previous
#include <cuda_runtime.h>
#include <stdint.h>

// Problem constants (fixed by the reference setup)
#define Bn 16
#define Pn 784
#define Dn 10000
#define Ln 1000
#define Cn 10

#define WSTRIDE 320   // padded words per row (320*32 = 10240 >= 10000)
#define NSLAB   10    // 10 slabs of 32 words each

// Scratch (allocation-free: device globals)
__device__ uint32_t g_vbits[Ln * WSTRIDE];   // sign bits of value_weight
__device__ uint32_t g_pbits[Pn * WSTRIDE];   // sign bits of position_weight
__device__ int      g_idx[Bn * Pn];          // level index per (b, pixel)
__device__ float    g_partial[NSLAB * Bn * Cn];
__device__ int      g_ctr;                   // last-CTA counter (reset each run)

// ---------------------------------------------------------------------------
// Kernel 1: compute idx, pack sign bits of both bipolar tables.
// Permuted bit layout: word w, bit l  <->  dim d = (w>>2)*128 + l*4 + (w&3).
// Warp-task = 512 dims: 4 lane-contiguous float4 loads (fully coalesced),
// sign extraction via FSETP feeding VOTE directly, 16 ballots -> 16 words.
// ---------------------------------------------------------------------------
__global__ void __launch_bounds__(256) pack_kernel(const float* __restrict__ x,
                                                   const float* __restrict__ posw,
                                                   const float* __restrict__ valw)
{
    const int tid     = blockIdx.x * blockDim.x + threadIdx.x;
    const int nthread = gridDim.x * blockDim.x;

    if (tid == 0) g_ctr = 0;   // reset fused-finalize counter for this replay

    // level index: idx = clamp(rint(x*999), 0, 999)  (rintf = half-to-even)
    for (int i = tid; i < Bn * Pn; i += nthread) {
        int q = (int)rintf(x[i] * 999.0f);
        g_idx[i] = min(max(q, 0), Ln - 1);
    }

    const int lane   = threadIdx.x & 31;
    const int warpId = tid >> 5;
    const int nWarps = nthread >> 5;
    const int totalTasks = (Ln + Pn) * 20;   // 20 x 512-dim tasks per row

    for (int task = warpId; task < totalTasks; task += nWarps) {
        int row = task / 20;
        int s   = task - row * 20;
        const float* src;
        uint32_t* dst;
        if (row < Ln) {
            src = valw + (size_t)row * Dn;
            dst = g_vbits + row * WSTRIDE;
        } else {
            src = posw + (size_t)(row - Ln) * Dn;
            dst = g_pbits + (row - Ln) * WSTRIDE;
        }

        uint32_t myword = 0;
        if (s < 19) {
            float4 v0 = *reinterpret_cast<const float4*>(src + s * 512 +   0 + lane * 4);
            float4 v1 = *reinterpret_cast<const float4*>(src + s * 512 + 128 + lane * 4);
            float4 v2 = *reinterpret_cast<const float4*>(src + s * 512 + 256 + lane * 4);
            float4 v3 = *reinterpret_cast<const float4*>(src + s * 512 + 384 + lane * 4);
#define PK(sub, vv)                                                          \
            {                                                                \
                uint32_t b0 = __ballot_sync(0xffffffffu, (vv).x < 0.0f);     \
                uint32_t b1 = __ballot_sync(0xffffffffu, (vv).y < 0.0f);     \
                uint32_t b2 = __ballot_sync(0xffffffffu, (vv).z < 0.0f);     \
                uint32_t b3 = __ballot_sync(0xffffffffu, (vv).w < 0.0f);     \
                if (lane == (sub)*4 + 0) myword = b0;                        \
                if (lane == (sub)*4 + 1) myword = b1;                        \
                if (lane == (sub)*4 + 2) myword = b2;                        \
                if (lane == (sub)*4 + 3) myword = b3;                        \
            }
            PK(0, v0) PK(1, v1) PK(2, v2) PK(3, v3)
#undef PK
        } else {
            // tail task (dims 9728..10239): per-lane validity
#pragma unroll
            for (int sub = 0; sub < 4; sub++) {
                int d0 = s * 512 + sub * 128 + lane * 4;
                bool valid = d0 < Dn;            // Dn % 4 == 0
                float4 v = make_float4(0.f, 0.f, 0.f, 0.f);
                if (valid) v = *reinterpret_cast<const float4*>(src + d0);
                uint32_t b0 = __ballot_sync(0xffffffffu, valid && v.x < 0.0f);
                uint32_t b1 = __ballot_sync(0xffffffffu, valid && v.y < 0.0f);
                uint32_t b2 = __ballot_sync(0xffffffffu, valid && v.z < 0.0f);
                uint32_t b3 = __ballot_sync(0xffffffffu, valid && v.w < 0.0f);
                if (lane == sub * 4 + 0) myword = b0;
                if (lane == sub * 4 + 1) myword = b1;
                if (lane == sub * 4 + 2) myword = b2;
                if (lane == sub * 4 + 3) myword = b3;
            }
        }
        if (lane < 16) dst[s * 16 + lane] = myword;      // coalesced 64B
    }
}

// ---------------------------------------------------------------------------
__device__ __forceinline__ void fadd(uint32_t a, uint32_t b, uint32_t cin,
                                     uint32_t& s, uint32_t& cout)
{
    uint32_t t = a ^ b;
    s    = t ^ cin;
    cout = (a & b) | (cin & t);
}

// ---------------------------------------------------------------------------
// Kernel 2: CTA = (batch, 32-word slab), 512 threads = 16 warps x 49 pixels.
// Warp lane = word within slab -> all bit-table loads 128B coalesced.
// 2-stage pipelined 7:3 CSA compressor; 16-warp smem reduction; threshold;
// COALESCED classify (warp per class, float4 loads + shfl-broadcast of enc
// words); fused last-CTA finalize. Fixed-order reductions, no float atomics.
// ---------------------------------------------------------------------------
__global__ void __launch_bounds__(512) hdc_main_kernel(const float* __restrict__ cw,
                                                       float* __restrict__ out)
{
    const int b    = blockIdx.x / NSLAB;
    const int slab = blockIdx.x - b * NSLAB;
    const int tid  = threadIdx.x;
    const int lane = tid & 31;
    const int warp = tid >> 5;                   // 0..15

    __shared__ int      sIdx[Pn];
    __shared__ uint32_t sRed[16][7][33];         // padded vs bank conflicts
    __shared__ uint32_t encW[32];
    __shared__ int      sLast;

    for (int i = tid; i < Pn; i += 512) sIdx[i] = g_idx[b * Pn + i];
    __syncthreads();

    const int w = slab * 32 + lane;

    uint32_t c[7];
#pragma unroll
    for (int j = 0; j < 7; j++) c[j] = 0u;

    const int p0 = warp * 49;
    const uint32_t* __restrict__ vb = g_vbits + w;
    const uint32_t* __restrict__ pb = g_pbits + w;

    // prologue: load group 0
    uint32_t t[7];
#pragma unroll
    for (int k = 0; k < 7; k++) {
        int lvl = sIdx[p0 + k];
        t[k] = __ldg(vb + lvl * WSTRIDE) ^ __ldg(pb + (p0 + k) * WSTRIDE);
    }

    for (int g = 0; g < 7; g++) {
        uint32_t tn[7];
        if (g < 6) {                             // prefetch next group
            const int pn = p0 + (g + 1) * 7;
#pragma unroll
            for (int k = 0; k < 7; k++) {
                int lvl = sIdx[pn + k];
                tn[k] = __ldg(vb + lvl * WSTRIDE) ^ __ldg(pb + (pn + k) * WSTRIDE);
            }
        }
        // 7:3 compressor -> (s3, s4, c4) with weights 1,2,4
        uint32_t s1, c1, s2, c2, s3, c3, s4, c4;
        fadd(t[0], t[1], t[2], s1, c1);
        fadd(t[3], t[4], t[5], s2, c2);
        fadd(s1,  s2,  t[6],  s3, c3);
        fadd(c1,  c2,  c3,    s4, c4);
        // merge 3-bit value into the 7-plane counter
        uint32_t carry = c[0] & s3; c[0] ^= s3;
        uint32_t s, co;
        fadd(c[1], s4, carry, s, co); c[1] = s; carry = co;
        fadd(c[2], c4, carry, s, co); c[2] = s; carry = co;
#pragma unroll
        for (int j = 3; j < 7; j++) { uint32_t nc = c[j] ^ carry; carry &= c[j]; c[j] = nc; }
#pragma unroll
        for (int k = 0; k < 7; k++) t[k] = tn[k];
    }

#pragma unroll
    for (int j = 0; j < 7; j++) sRed[warp][j][lane] = c[j];
    __syncthreads();

    if (warp == 0) {
        uint32_t a[10];
#pragma unroll
        for (int j = 0; j < 7; j++) a[j] = sRed[0][j][lane];
        a[7] = a[8] = a[9] = 0u;
#pragma unroll
        for (int wu = 1; wu < 16; wu++) {
            uint32_t carry = 0u;
#pragma unroll
            for (int j = 0; j < 7; j++) {
                uint32_t s, co;
                fadd(a[j], sRed[wu][j][lane], carry, s, co);
                a[j] = s; carry = co;
            }
#pragma unroll
            for (int j = 7; j < 10; j++) { uint32_t nc = a[j] ^ carry; carry &= a[j]; a[j] = nc; }
        }
        // enc = +1 iff count < 392 (392 = 0b0110001000)
        uint32_t eq = ~0u, lt = 0u;
        eq &= ~a[9];
        lt |= eq & ~a[8]; eq &= a[8];
        lt |= eq & ~a[7]; eq &= a[7];
        eq &= ~a[6]; eq &= ~a[5]; eq &= ~a[4];
        lt |= eq & ~a[3];
        encW[lane] = lt;                         // bit set -> enc = +1
    }
    __syncthreads();

    // ---- coalesced classify: warp cc (<10) handles class cc over this slab.
    // float4 at dims [d0, d0+3] (d0 = slab*1024 + i*128 + lane*4) maps to
    // bit ((d0>>2)&31)==lane of words i*4+{0..3}; get words via shfl.
    if (warp < Cn) {
        const uint32_t encReg = encW[lane];
        const float* __restrict__ wrow = cw + warp * Dn + slab * 1024;
        float acc = 0.0f;
#pragma unroll
        for (int i = 0; i < 8; i++) {
            uint32_t w0 = __shfl_sync(0xffffffffu, encReg, i * 4 + 0);
            uint32_t w1 = __shfl_sync(0xffffffffu, encReg, i * 4 + 1);
            uint32_t w2 = __shfl_sync(0xffffffffu, encReg, i * 4 + 2);
            uint32_t w3 = __shfl_sync(0xffffffffu, encReg, i * 4 + 3);
            int d0 = slab * 1024 + i * 128 + lane * 4;
            if (d0 < Dn) {                       // Dn%4==0 -> whole float4 valid
                float4 v = *reinterpret_cast<const float4*>(wrow + i * 128 + lane * 4);
                acc += ((w0 >> lane) & 1u) ? v.x : -v.x;
                acc += ((w1 >> lane) & 1u) ? v.y : -v.y;
                acc += ((w2 >> lane) & 1u) ? v.z : -v.z;
                acc += ((w3 >> lane) & 1u) ? v.w : -v.w;
            }
        }
        // deterministic fixed-order warp reduction
#pragma unroll
        for (int off = 16; off >= 1; off >>= 1)
            acc += __shfl_xor_sync(0xffffffffu, acc, off);
        if (lane == 0) g_partial[(slab * Bn + b) * Cn + warp] = acc;
    }

    // ---- fused finalize: last CTA reduces g_partial and writes out ----
    __syncthreads();
    if (tid == 0) {
        __threadfence();                         // publish g_partial writes
        int prev = atomicAdd(&g_ctr, 1);
        sLast = (prev == Bn * NSLAB - 1);
    }
    __syncthreads();
    if (sLast) {
        __threadfence();                         // acquire all g_partial
        if (tid < Bn * Cn) {
            float s = 0.0f;
#pragma unroll
            for (int sl = 0; sl < NSLAB; sl++) s += g_partial[sl * Bn * Cn + tid];
            out[tid] = s;
        }
        if (tid == 0) g_ctr = 0;                 // reset for next replay
    }
}

// ---------------------------------------------------------------------------
extern "C" void kernel_launch(void* const* d_in, const int* in_sizes, int n_in,
                              void* d_out, int out_size)
{
    const float* x    = (const float*)d_in[0];   // [16,28,28]
    const float* posw = (const float*)d_in[1];   // [784,10000]
    const float* valw = (const float*)d_in[2];   // [1000,10000]
    const float* cw   = (const float*)d_in[3];   // [10,10000]
    float* out = (float*)d_out;                  // [16,10]

    pack_kernel<<<1184, 256>>>(x, posw, valw);
    hdc_main_kernel<<<Bn * NSLAB, 512>>>(cw, out);
}